// round 1
// baseline (speedup 1.0000x reference)
#include <cuda_runtime.h>

// Problem constants (from reference setup_inputs): b=1, n=4 views, f=8 frames,
// l=256, C=320, heads=8, head_dim=40. After rearrange: BF=8 batches, L=1024.
#define C       320
#define L       1024
#define H       8
#define D       40
#define BFRM    8
#define ROWS    (BFRM * L)   // 8192

// ---- scratch (no allocations allowed) ----
__device__ float g_Q   [ROWS * C];
__device__ float g_K   [ROWS * C];
__device__ float g_V   [ROWS * C];
__device__ float g_Qi  [ROWS * C];
__device__ float g_base[ROWS * C];
__device__ float g_iat [ROWS * C];
__device__ float g_tmp [ROWS * C];

// map logical h-row g (bf*1024 + n*256 + l) -> hidden_states row ((n*8+bf)*256 + l)
__device__ __forceinline__ int hidden_row(int g) {
    int bf = g >> 10;
    int r  = g & 1023;
    int n  = r >> 8;
    int l  = r & 255;
    return ((n << 3) + bf) * 256 + l;
}

// ============================================================================
// Kernel 1: fused projection GEMM. Y_w = gather(hidden) @ W_w  for
// w in {Wq, Wk, Wv, Wq_i2v}. 64x64 tile, BK=16, 256 threads, 4x4 per thread.
// ============================================================================
__global__ __launch_bounds__(256) void proj_kernel(
    const float* __restrict__ hidden,
    const float* __restrict__ Wq, const float* __restrict__ Wk,
    const float* __restrict__ Wv, const float* __restrict__ Wqi)
{
    const float* W;
    float* Y;
    switch (blockIdx.z) {
        case 0:  W = Wq;  Y = g_Q;  break;
        case 1:  W = Wk;  Y = g_K;  break;
        case 2:  W = Wv;  Y = g_V;  break;
        default: W = Wqi; Y = g_Qi; break;
    }
    __shared__ float As[16][64];
    __shared__ float Bs[16][64];
    int t  = threadIdx.x;
    int m0 = blockIdx.x * 64, n0 = blockIdx.y * 64;
    int ty = t >> 4, tx = t & 15;
    int am = t >> 2, ak = (t & 3) * 4;
    const float* aptr = hidden + (size_t)hidden_row(m0 + am) * C;
    int nb = t & 63, kb = t >> 6;

    float acc[4][4];
#pragma unroll
    for (int i = 0; i < 4; i++)
#pragma unroll
        for (int j = 0; j < 4; j++) acc[i][j] = 0.f;

    for (int k0 = 0; k0 < C; k0 += 16) {
        float4 av = *(const float4*)(aptr + k0 + ak);
        As[ak    ][am] = av.x;
        As[ak + 1][am] = av.y;
        As[ak + 2][am] = av.z;
        As[ak + 3][am] = av.w;
#pragma unroll
        for (int i = 0; i < 4; i++)
            Bs[kb + 4 * i][nb] = W[(size_t)(k0 + kb + 4 * i) * C + n0 + nb];
        __syncthreads();
#pragma unroll
        for (int kk = 0; kk < 16; kk++) {
            float4 a = *(const float4*)&As[kk][ty * 4];
            float4 b = *(const float4*)&Bs[kk][tx * 4];
            acc[0][0] += a.x * b.x; acc[0][1] += a.x * b.y; acc[0][2] += a.x * b.z; acc[0][3] += a.x * b.w;
            acc[1][0] += a.y * b.x; acc[1][1] += a.y * b.y; acc[1][2] += a.y * b.z; acc[1][3] += a.y * b.w;
            acc[2][0] += a.z * b.x; acc[2][1] += a.z * b.y; acc[2][2] += a.z * b.z; acc[2][3] += a.z * b.w;
            acc[3][0] += a.w * b.x; acc[3][1] += a.w * b.y; acc[3][2] += a.w * b.z; acc[3][3] += a.w * b.w;
        }
        __syncthreads();
    }
#pragma unroll
    for (int i = 0; i < 4; i++) {
        float4 v = make_float4(acc[i][0], acc[i][1], acc[i][2], acc[i][3]);
        *(float4*)&Y[(size_t)(m0 + ty * 4 + i) * C + n0 + tx * 4] = v;
    }
}

// ============================================================================
// Kernel 2/3: flash-style attention. One thread = one query row (head-sliced),
// K/V staged in smem tiles of 128 rows. Online softmax with rare-rescale.
// i2v==1 -> use g_Qi as Q, frame-0 KV for all frames, write g_iat.
// ============================================================================
__global__ __launch_bounds__(128) void attn_kernel(int i2v)
{
    int bf = blockIdx.z, h = blockIdx.y;
    int qg = bf * L + blockIdx.x * 128 + threadIdx.x;
    int kv_bf = i2v ? 0 : bf;
    const float* Qsrc = i2v ? g_Qi : g_Q;
    float* O = i2v ? g_iat : g_base;

    const float scale = 0.158113883f;  // 1/sqrt(40)
    float q[D];
    {
        const float* qp = Qsrc + (size_t)qg * C + h * D;
#pragma unroll
        for (int j = 0; j < D; j += 4) {
            float4 v = *(const float4*)(qp + j);
            q[j] = v.x * scale; q[j + 1] = v.y * scale;
            q[j + 2] = v.z * scale; q[j + 3] = v.w * scale;
        }
    }

    __shared__ float Ks[128][40];
    __shared__ float Vs[128][40];

    float m = -1e30f, lsum = 0.f;
    float acc[D];
#pragma unroll
    for (int j = 0; j < D; j++) acc[j] = 0.f;

    for (int kt = 0; kt < 8; kt++) {
        const size_t kvrow0 = (size_t)(kv_bf * L + kt * 128);
        const float* Kb = g_K + kvrow0 * C + h * D;
        const float* Vb = g_V + kvrow0 * C + h * D;
        __syncthreads();  // previous tile fully consumed
        for (int e = threadIdx.x; e < 1280; e += 128) {
            int r  = e / 10;
            int c4 = (e - r * 10) * 4;
            *(float4*)&Ks[r][c4] = *(const float4*)(Kb + (size_t)r * C + c4);
            *(float4*)&Vs[r][c4] = *(const float4*)(Vb + (size_t)r * C + c4);
        }
        __syncthreads();

#pragma unroll 2
        for (int kk = 0; kk < 128; kk++) {
            const float4* kr = (const float4*)Ks[kk];
            float s0 = 0.f, s1 = 0.f, s2 = 0.f, s3 = 0.f;
#pragma unroll
            for (int j4 = 0; j4 < 10; j4++) {
                float4 kv = kr[j4];
                s0 += q[4 * j4    ] * kv.x;
                s1 += q[4 * j4 + 1] * kv.y;
                s2 += q[4 * j4 + 2] * kv.z;
                s3 += q[4 * j4 + 3] * kv.w;
            }
            float s = (s0 + s1) + (s2 + s3);
            if (s > m) {                      // rare (~7 times per 1024 keys)
                float corr = __expf(m - s);
                lsum *= corr;
#pragma unroll
                for (int j = 0; j < D; j++) acc[j] *= corr;
                m = s;
            }
            float p = __expf(s - m);
            lsum += p;
            const float4* vr = (const float4*)Vs[kk];
#pragma unroll
            for (int j4 = 0; j4 < 10; j4++) {
                float4 vv = vr[j4];
                acc[4 * j4    ] += p * vv.x;
                acc[4 * j4 + 1] += p * vv.y;
                acc[4 * j4 + 2] += p * vv.z;
                acc[4 * j4 + 3] += p * vv.w;
            }
        }
    }

    float inv = __fdividef(1.f, lsum);
    float* op = O + (size_t)qg * C + h * D;
#pragma unroll
    for (int j = 0; j < D; j += 4) {
        float4 v = make_float4(acc[j] * inv, acc[j + 1] * inv,
                               acc[j + 2] * inv, acc[j + 3] * inv);
        *(float4*)(op + j) = v;
    }
}

// ============================================================================
// Kernel 4: g_tmp = g_base + g_iat @ Wo_i2v + bo_i2v
// ============================================================================
__global__ __launch_bounds__(256) void ep1_kernel(
    const float* __restrict__ Woi, const float* __restrict__ boi)
{
    __shared__ float As[16][64];
    __shared__ float Bs[16][64];
    int t  = threadIdx.x;
    int m0 = blockIdx.x * 64, n0 = blockIdx.y * 64;
    int ty = t >> 4, tx = t & 15;
    int am = t >> 2, ak = (t & 3) * 4;
    const float* aptr = g_iat + (size_t)(m0 + am) * C;
    int nb = t & 63, kb = t >> 6;

    float acc[4][4];
#pragma unroll
    for (int i = 0; i < 4; i++)
#pragma unroll
        for (int j = 0; j < 4; j++) acc[i][j] = 0.f;

    for (int k0 = 0; k0 < C; k0 += 16) {
        float4 av = *(const float4*)(aptr + k0 + ak);
        As[ak][am] = av.x; As[ak + 1][am] = av.y;
        As[ak + 2][am] = av.z; As[ak + 3][am] = av.w;
#pragma unroll
        for (int i = 0; i < 4; i++)
            Bs[kb + 4 * i][nb] = Woi[(size_t)(k0 + kb + 4 * i) * C + n0 + nb];
        __syncthreads();
#pragma unroll
        for (int kk = 0; kk < 16; kk++) {
            float4 a = *(const float4*)&As[kk][ty * 4];
            float4 b = *(const float4*)&Bs[kk][tx * 4];
            acc[0][0] += a.x * b.x; acc[0][1] += a.x * b.y; acc[0][2] += a.x * b.z; acc[0][3] += a.x * b.w;
            acc[1][0] += a.y * b.x; acc[1][1] += a.y * b.y; acc[1][2] += a.y * b.z; acc[1][3] += a.y * b.w;
            acc[2][0] += a.z * b.x; acc[2][1] += a.z * b.y; acc[2][2] += a.z * b.z; acc[2][3] += a.z * b.w;
            acc[3][0] += a.w * b.x; acc[3][1] += a.w * b.y; acc[3][2] += a.w * b.z; acc[3][3] += a.w * b.w;
        }
        __syncthreads();
    }
    int gn = n0 + tx * 4;
    float4 bv = *(const float4*)&boi[gn];
#pragma unroll
    for (int i = 0; i < 4; i++) {
        int gm = m0 + ty * 4 + i;
        float4 ad = *(const float4*)&g_base[(size_t)gm * C + gn];
        float4 v = make_float4(acc[i][0] + ad.x + bv.x,
                               acc[i][1] + ad.y + bv.y,
                               acc[i][2] + ad.z + bv.z,
                               acc[i][3] + ad.w + bv.w);
        *(float4*)&g_tmp[(size_t)gm * C + gn] = v;
    }
}

// ============================================================================
// Kernel 5: out = g_tmp @ Wo + bo, scattered back to (b n f) l c layout.
// ============================================================================
__global__ __launch_bounds__(256) void ep2_kernel(
    const float* __restrict__ Wo, const float* __restrict__ bo,
    float* __restrict__ out)
{
    __shared__ float As[16][64];
    __shared__ float Bs[16][64];
    int t  = threadIdx.x;
    int m0 = blockIdx.x * 64, n0 = blockIdx.y * 64;
    int ty = t >> 4, tx = t & 15;
    int am = t >> 2, ak = (t & 3) * 4;
    const float* aptr = g_tmp + (size_t)(m0 + am) * C;
    int nb = t & 63, kb = t >> 6;

    float acc[4][4];
#pragma unroll
    for (int i = 0; i < 4; i++)
#pragma unroll
        for (int j = 0; j < 4; j++) acc[i][j] = 0.f;

    for (int k0 = 0; k0 < C; k0 += 16) {
        float4 av = *(const float4*)(aptr + k0 + ak);
        As[ak][am] = av.x; As[ak + 1][am] = av.y;
        As[ak + 2][am] = av.z; As[ak + 3][am] = av.w;
#pragma unroll
        for (int i = 0; i < 4; i++)
            Bs[kb + 4 * i][nb] = Wo[(size_t)(k0 + kb + 4 * i) * C + n0 + nb];
        __syncthreads();
#pragma unroll
        for (int kk = 0; kk < 16; kk++) {
            float4 a = *(const float4*)&As[kk][ty * 4];
            float4 b = *(const float4*)&Bs[kk][tx * 4];
            acc[0][0] += a.x * b.x; acc[0][1] += a.x * b.y; acc[0][2] += a.x * b.z; acc[0][3] += a.x * b.w;
            acc[1][0] += a.y * b.x; acc[1][1] += a.y * b.y; acc[1][2] += a.y * b.z; acc[1][3] += a.y * b.w;
            acc[2][0] += a.z * b.x; acc[2][1] += a.z * b.y; acc[2][2] += a.z * b.z; acc[2][3] += a.z * b.w;
            acc[3][0] += a.w * b.x; acc[3][1] += a.w * b.y; acc[3][2] += a.w * b.z; acc[3][3] += a.w * b.w;
        }
        __syncthreads();
    }
    int gn = n0 + tx * 4;
    float4 bv = *(const float4*)&bo[gn];
#pragma unroll
    for (int i = 0; i < 4; i++) {
        int gm = m0 + ty * 4 + i;
        int orow = hidden_row(gm);  // inverse rearrange on store
        float4 v = make_float4(acc[i][0] + bv.x, acc[i][1] + bv.y,
                               acc[i][2] + bv.z, acc[i][3] + bv.w);
        *(float4*)&out[(size_t)orow * C + gn] = v;
    }
}

// ============================================================================
extern "C" void kernel_launch(void* const* d_in, const int* in_sizes, int n_in,
                              void* d_out, int out_size)
{
    const float* hidden = (const float*)d_in[0];
    const float* Wq  = (const float*)d_in[1];
    const float* Wk  = (const float*)d_in[2];
    const float* Wv  = (const float*)d_in[3];
    const float* Wo  = (const float*)d_in[4];
    const float* bo  = (const float*)d_in[5];
    const float* Wqi = (const float*)d_in[6];
    const float* Woi = (const float*)d_in[7];
    const float* boi = (const float*)d_in[8];
    float* out = (float*)d_out;

    // 1) Q, K, V, Q_i2v projections (gathered A)
    proj_kernel<<<dim3(ROWS / 64, C / 64, 4), 256>>>(hidden, Wq, Wk, Wv, Wqi);
    // 2) base attention
    attn_kernel<<<dim3(L / 128, H, BFRM), 128>>>(0);
    // 3) i2v attention (frame-0 KV broadcast)
    attn_kernel<<<dim3(L / 128, H, BFRM), 128>>>(1);
    // 4) tmp = base + i2v @ Wo_i2v + bo_i2v
    ep1_kernel<<<dim3(ROWS / 64, C / 64), 256>>>(Woi, boi);
    // 5) out = tmp @ Wo + bo (scatter to output layout)
    ep2_kernel<<<dim3(ROWS / 64, C / 64), 256>>>(Wo, bo, out);
}